// round 1
// baseline (speedup 1.0000x reference)
#include <cuda_runtime.h>
#include <cuda_bf16.h>
#include <stdint.h>

#define NB     4096
#define NROWS  8192       // 2B
#define DD     128
#define BM     128
#define BN     128
#define JSPLIT 4
#define LDSTR  136        // smem row stride (bf16 elems), pad 8 -> conflict-free

__device__ __align__(16) float           d_z [NROWS * DD];
__device__ __align__(16) __nv_bfloat16   d_zb[NROWS * DD];
__device__ float d_S  [NROWS];
__device__ float d_pos[NB];

// ---------------------------------------------------------------- zero S
__global__ void zero_kernel() {
    int i = blockIdx.x * blockDim.x + threadIdx.x;
    if (i < NROWS) d_S[i] = 0.0f;
}

// ---------------------------------------------------------------- normalize
// one warp per row: fp32 z and bf16 copy
__global__ void normalize_kernel(const float* __restrict__ xi,
                                 const float* __restrict__ xj) {
    int warp = (blockIdx.x * blockDim.x + threadIdx.x) >> 5;
    int lane = threadIdx.x & 31;
    if (warp >= NROWS) return;
    const float* src = (warp < NB) ? (xi + (size_t)warp * DD)
                                   : (xj + (size_t)(warp - NB) * DD);
    float4 v = ((const float4*)src)[lane];          // 32 lanes * 4 = 128
    float s = v.x*v.x + v.y*v.y + v.z*v.z + v.w*v.w;
    #pragma unroll
    for (int o = 16; o; o >>= 1) s += __shfl_xor_sync(0xffffffffu, s, o);
    float inv = 1.0f / fmaxf(sqrtf(s), 1e-12f);
    float4 z; z.x = v.x*inv; z.y = v.y*inv; z.z = v.z*inv; z.w = v.w*inv;
    ((float4*)(d_z + (size_t)warp * DD))[lane] = z;
    __nv_bfloat162* zb = (__nv_bfloat162*)(d_zb + (size_t)warp * DD);
    zb[lane*2 + 0] = __floats2bfloat162_rn(z.x, z.y);
    zb[lane*2 + 1] = __floats2bfloat162_rn(z.z, z.w);
}

// ---------------------------------------------------------------- positives (fp32 exact)
__global__ void pos_kernel() {
    int warp = (blockIdx.x * blockDim.x + threadIdx.x) >> 5;
    int lane = threadIdx.x & 31;
    if (warp >= NB) return;
    float4 a = ((const float4*)(d_z + (size_t)warp        * DD))[lane];
    float4 b = ((const float4*)(d_z + (size_t)(warp + NB) * DD))[lane];
    float s = a.x*b.x + a.y*b.y + a.z*b.z + a.w*b.w;
    #pragma unroll
    for (int o = 16; o; o >>= 1) s += __shfl_xor_sync(0xffffffffu, s, o);
    if (lane == 0) d_pos[warp] = s;
}

// ---------------------------------------------------------------- fused sim -> exp -> rowsum
// grid (NROWS/BM, JSPLIT). 8 warps: 4 (m) x 2 (n), warp tile 32x64.
// mma.sync.m16n8k16 bf16, fp32 accum. Diagonal excluded exactly.
__device__ __forceinline__ void mma16816(float c[4], const uint32_t a[4],
                                         const uint32_t b[2]) {
    asm volatile(
        "mma.sync.aligned.m16n8k16.row.col.f32.bf16.bf16.f32 "
        "{%0,%1,%2,%3}, {%4,%5,%6,%7}, {%8,%9}, {%0,%1,%2,%3};\n"
        : "+f"(c[0]), "+f"(c[1]), "+f"(c[2]), "+f"(c[3])
        : "r"(a[0]), "r"(a[1]), "r"(a[2]), "r"(a[3]), "r"(b[0]), "r"(b[1]));
}

__global__ void __launch_bounds__(256, 2) sim_kernel() {
    extern __shared__ __nv_bfloat16 smem[];
    __nv_bfloat16* As = smem;                    // [BM][LDSTR]
    __nv_bfloat16* Bs = smem + BM * LDSTR;       // [BN][LDSTR]

    const int tid    = threadIdx.x;
    const int wid    = tid >> 5;
    const int lane   = tid & 31;
    const int g      = lane >> 2;     // group row 0..7
    const int q      = lane & 3;      // quad col  0..3
    const int warp_m = wid & 3;       // 0..3
    const int warp_n = wid >> 2;      // 0..1
    const int ibase  = blockIdx.x * BM;
    const int j0     = blockIdx.y * (NROWS / JSPLIT);

    // load A tile once (128x128 bf16, uint4 chunks)
    for (int c = tid; c < BM * DD / 8; c += 256) {
        int row = c >> 4, c8 = c & 15;
        *(uint4*)(As + row * LDSTR + c8 * 8) =
            *(const uint4*)(d_zb + (size_t)(ibase + row) * DD + c8 * 8);
    }

    float rowsum[2][2] = {{0.f, 0.f}, {0.f, 0.f}};
    const int JT = NROWS / JSPLIT / BN;          // 16

    for (int jt = 0; jt < JT; ++jt) {
        const int jbase = j0 + jt * BN;
        __syncthreads();                         // Bs consumers done
        for (int c = tid; c < BN * DD / 8; c += 256) {
            int row = c >> 4, c8 = c & 15;
            *(uint4*)(Bs + row * LDSTR + c8 * 8) =
                *(const uint4*)(d_zb + (size_t)(jbase + row) * DD + c8 * 8);
        }
        __syncthreads();

        float acc[2][8][4];
        #pragma unroll
        for (int mf = 0; mf < 2; mf++)
            #pragma unroll
            for (int nf = 0; nf < 8; nf++)
                #pragma unroll
                for (int e = 0; e < 4; e++) acc[mf][nf][e] = 0.f;

        #pragma unroll
        for (int kk = 0; kk < 8; kk++) {
            const int kb = kk * 16;
            uint32_t a[2][4], b[8][2];
            #pragma unroll
            for (int mf = 0; mf < 2; mf++) {
                const __nv_bfloat16* p =
                    As + (warp_m * 32 + mf * 16 + g) * LDSTR + kb + 2 * q;
                a[mf][0] = *(const uint32_t*)p;
                a[mf][1] = *(const uint32_t*)(p + 8 * LDSTR);
                a[mf][2] = *(const uint32_t*)(p + 8);
                a[mf][3] = *(const uint32_t*)(p + 8 * LDSTR + 8);
            }
            #pragma unroll
            for (int nf = 0; nf < 8; nf++) {
                const __nv_bfloat16* p =
                    Bs + (warp_n * 64 + nf * 8 + g) * LDSTR + kb + 2 * q;
                b[nf][0] = *(const uint32_t*)p;
                b[nf][1] = *(const uint32_t*)(p + 8);
            }
            #pragma unroll
            for (int mf = 0; mf < 2; mf++)
                #pragma unroll
                for (int nf = 0; nf < 8; nf++)
                    mma16816(acc[mf][nf], a[mf], b[nf]);
        }

        // exp + rowsum, excluding diagonal exactly
        #pragma unroll
        for (int mf = 0; mf < 2; mf++) {
            #pragma unroll
            for (int nf = 0; nf < 8; nf++) {
                #pragma unroll
                for (int e = 0; e < 4; e++) {
                    int rg = ibase + warp_m * 32 + mf * 16 + g + ((e >> 1) << 3);
                    int cg = jbase + warp_n * 64 + nf * 8 + q * 2 + (e & 1);
                    float ev = (rg == cg) ? 0.f : __expf(acc[mf][nf][e] * 10.0f);
                    rowsum[mf][e >> 1] += ev;
                }
            }
        }
    }

    // reduce partial rowsums across the quad, atomically accumulate
    #pragma unroll
    for (int mf = 0; mf < 2; mf++) {
        #pragma unroll
        for (int h = 0; h < 2; h++) {
            float s = rowsum[mf][h];
            s += __shfl_xor_sync(0xffffffffu, s, 1);
            s += __shfl_xor_sync(0xffffffffu, s, 2);
            if (q == 0)
                atomicAdd(&d_S[ibase + warp_m * 32 + mf * 16 + g + h * 8], s);
        }
    }
}

// ---------------------------------------------------------------- final reduce
__global__ void final_kernel(float* out) {
    __shared__ double red[256];
    int tid = threadIdx.x;
    double s = 0.0;
    for (int r = tid; r < NROWS; r += 256) s += (double)logf(d_S[r]);
    for (int i = tid; i < NB;    i += 256) s -= 20.0 * (double)d_pos[i];
    red[tid] = s;
    __syncthreads();
    #pragma unroll
    for (int st = 128; st; st >>= 1) {
        if (tid < st) red[tid] += red[tid + st];
        __syncthreads();
    }
    if (tid == 0) out[0] = (float)(red[0] / (double)NROWS);
}

// ---------------------------------------------------------------- launch
extern "C" void kernel_launch(void* const* d_in, const int* in_sizes, int n_in,
                              void* d_out, int out_size) {
    const float* xi = (const float*)d_in[0];
    const float* xj = (const float*)d_in[1];
    float* out = (float*)d_out;

    const int smem_bytes = 2 * BM * LDSTR * (int)sizeof(__nv_bfloat16); // 69632
    cudaFuncSetAttribute(sim_kernel,
                         cudaFuncAttributeMaxDynamicSharedMemorySize, smem_bytes);

    zero_kernel<<<(NROWS + 255) / 256, 256>>>();
    normalize_kernel<<<NROWS / 8, 256>>>(xi, xj);
    pos_kernel<<<NB / 8, 256>>>();
    dim3 grid(NROWS / BM, JSPLIT);
    sim_kernel<<<grid, 256, smem_bytes>>>();
    final_kernel<<<1, 256>>>(out);
}

// round 3
// speedup vs baseline: 1.4310x; 1.4310x over previous
#include <cuda_runtime.h>
#include <cuda_bf16.h>
#include <stdint.h>

#define NB     4096
#define NROWS  8192
#define DD     128
#define BM     128
#define BN     128
#define JSPLIT 4
#define JT     (NROWS / JSPLIT / BN)   // 16
#define LDSTR  136                      // fallback smem stride

// tcgen05 only exists in the arch-specific (sm_103a/sm_100a) compilation pass.
#if !defined(__CUDA_ARCH__) || defined(__CUDA_ARCH_FEAT_SM103_ALL) || \
    defined(__CUDA_ARCH_FEAT_SM100_ALL) || defined(__CUDA_ARCH_SPECIFIC__) || \
    defined(__CUDA_ARCH_FAMILY_SPECIFIC__)
#define HAS_TC 1
#else
#define HAS_TC 0
#endif

__device__ __align__(16) float          d_z [NROWS * DD];
__device__ __align__(16) __nv_bfloat16  d_zb[NROWS * DD];
__device__ float d_S  [NROWS];
__device__ float d_pos[NB];

// ------------------------------------------------------------------ utils
__device__ __forceinline__ uint32_t smem_u32(const void* p) {
    uint32_t a;
    asm("{ .reg .u64 t; cvta.to.shared.u64 t, %1; cvt.u32.u64 %0, t; }"
        : "=r"(a) : "l"(p));
    return a;
}
__device__ __forceinline__ float ex2f(float x) {
    float y; asm("ex2.approx.ftz.f32 %0, %1;" : "=f"(y) : "f"(x)); return y;
}

// ------------------------------------------------------------------ normalize (+zero S)
__global__ void normalize_kernel(const float* __restrict__ xi,
                                 const float* __restrict__ xj) {
    int t = blockIdx.x * blockDim.x + threadIdx.x;
    if (t < NROWS) d_S[t] = 0.0f;
    int warp = t >> 5;
    int lane = threadIdx.x & 31;
    if (warp >= NROWS) return;
    const float* src = (warp < NB) ? (xi + (size_t)warp * DD)
                                   : (xj + (size_t)(warp - NB) * DD);
    float4 v = ((const float4*)src)[lane];
    float s = v.x*v.x + v.y*v.y + v.z*v.z + v.w*v.w;
    #pragma unroll
    for (int o = 16; o; o >>= 1) s += __shfl_xor_sync(0xffffffffu, s, o);
    float inv = 1.0f / fmaxf(sqrtf(s), 1e-12f);
    float4 z; z.x = v.x*inv; z.y = v.y*inv; z.z = v.z*inv; z.w = v.w*inv;
    ((float4*)(d_z + (size_t)warp * DD))[lane] = z;
    __nv_bfloat162* zb = (__nv_bfloat162*)(d_zb + (size_t)warp * DD);
    zb[lane*2 + 0] = __floats2bfloat162_rn(z.x, z.y);
    zb[lane*2 + 1] = __floats2bfloat162_rn(z.z, z.w);
}

// ------------------------------------------------------------------ positives (fp32)
__global__ void pos_kernel() {
    int warp = (blockIdx.x * blockDim.x + threadIdx.x) >> 5;
    int lane = threadIdx.x & 31;
    if (warp >= NB) return;
    float4 a = ((const float4*)(d_z + (size_t)warp        * DD))[lane];
    float4 b = ((const float4*)(d_z + (size_t)(warp + NB) * DD))[lane];
    float s = a.x*b.x + a.y*b.y + a.z*b.z + a.w*b.w;
    #pragma unroll
    for (int o = 16; o; o >>= 1) s += __shfl_xor_sync(0xffffffffu, s, o);
    if (lane == 0) d_pos[warp] = s;
}

// ================================================================== tcgen05 path
#if HAS_TC
// SW128 K-major descriptor base: layout=SW128, version=1, SBO=64, LBO=1
#define DESC_BASE ((2ull << 61) | (1ull << 46) | (64ull << 32) | (1ull << 16))
__device__ __forceinline__ uint64_t make_desc(uint32_t addr) {
    return DESC_BASE | ((uint64_t)(addr >> 4) & 0x3FFF);
}
// idesc kind::f16: dtype=F32, a=BF16, b=BF16 (K-major), N=128, M=128
#define MMA_IDESC 0x8200490u

__device__ __forceinline__ void mma_f16_ss(uint32_t d, uint64_t a, uint64_t b,
                                           uint32_t en) {
    asm volatile(
        "{\n\t.reg .pred p;\n\t"
        "setp.ne.u32 p, %4, 0;\n\t"
        "tcgen05.mma.cta_group::1.kind::f16 [%0], %1, %2, %3, {%5,%5,%5,%5}, p;\n\t}"
        :: "r"(d), "l"(a), "l"(b), "r"(MMA_IDESC), "r"(en), "r"(0u) : "memory");
}

#define MBAR_INIT(a)   asm volatile("mbarrier.init.shared.b64 [%0], 1;" :: "r"(a) : "memory")
#define MBAR_INVAL(a)  asm volatile("mbarrier.inval.shared.b64 [%0];"   :: "r"(a) : "memory")
#define TC_COMMIT(a)   asm volatile("tcgen05.commit.cta_group::1.mbarrier::arrive::one.shared::cluster.b64 [%0];" :: "r"(a) : "memory")
#define TC_FENCE_AFTER()  asm volatile("tcgen05.fence::after_thread_sync;"  ::: "memory")
#define TC_FENCE_BEFORE() asm volatile("tcgen05.fence::before_thread_sync;" ::: "memory")
#define TC_WAIT_LD()      asm volatile("tcgen05.wait::ld.sync.aligned;"     ::: "memory")
#define FENCE_ASYNC()     asm volatile("fence.proxy.async.shared::cta;"     ::: "memory")

__device__ __forceinline__ void mbar_wait(uint32_t mbar, uint32_t parity) {
    uint32_t done;
    asm volatile(
        "{\n\t.reg .pred p;\n\t"
        "mbarrier.try_wait.parity.acquire.cta.shared::cta.b64 p, [%1], %2;\n\t"
        "selp.b32 %0, 1, 0, p;\n\t}"
        : "=r"(done) : "r"(mbar), "r"(parity) : "memory");
    if (!done) {
        asm volatile(
            "{\n\t.reg .pred P1;\n\t"
            "WL_%=:\n\t"
            "mbarrier.try_wait.parity.acquire.cta.shared::cta.b64 P1, [%0], %1, 0x989680;\n\t"
            "@P1 bra.uni WD_%=;\n\t"
            "bra.uni WL_%=;\n\t"
            "WD_%=:\n\t}"
            :: "r"(mbar), "r"(parity) : "memory");
    }
}

#define LDTM_X32(r, a) \
    asm volatile("tcgen05.ld.sync.aligned.32x32b.x32.b32 " \
        "{%0,%1,%2,%3,%4,%5,%6,%7,%8,%9,%10,%11,%12,%13,%14,%15," \
        "%16,%17,%18,%19,%20,%21,%22,%23,%24,%25,%26,%27,%28,%29,%30,%31}, [%32];" \
        : "=r"((r)[0]),"=r"((r)[1]),"=r"((r)[2]),"=r"((r)[3]), \
          "=r"((r)[4]),"=r"((r)[5]),"=r"((r)[6]),"=r"((r)[7]), \
          "=r"((r)[8]),"=r"((r)[9]),"=r"((r)[10]),"=r"((r)[11]), \
          "=r"((r)[12]),"=r"((r)[13]),"=r"((r)[14]),"=r"((r)[15]), \
          "=r"((r)[16]),"=r"((r)[17]),"=r"((r)[18]),"=r"((r)[19]), \
          "=r"((r)[20]),"=r"((r)[21]),"=r"((r)[22]),"=r"((r)[23]), \
          "=r"((r)[24]),"=r"((r)[25]),"=r"((r)[26]),"=r"((r)[27]), \
          "=r"((r)[28]),"=r"((r)[29]),"=r"((r)[30]),"=r"((r)[31]) \
        : "r"(a))
#endif  // HAS_TC

// blocked-atom SW128 byte offset for (row, 16B-chunk) of a 128x128 bf16 tile
__device__ __forceinline__ uint32_t tile_off(int row, int c16) {
    uint32_t byte = (uint32_t)(((row >> 3) + ((c16 >> 3) << 4)) * 1024
                               + (row & 7) * 128 + (c16 & 7) * 16);
    return byte ^ ((byte >> 3) & 0x70);
}

#if !HAS_TC
// fallback HMMA primitive (sm_103 pass only)
__device__ __forceinline__ void mma16816(float c[4], const uint32_t a[4],
                                         const uint32_t b[2]) {
    asm volatile(
        "mma.sync.aligned.m16n8k16.row.col.f32.bf16.bf16.f32 "
        "{%0,%1,%2,%3}, {%4,%5,%6,%7}, {%8,%9}, {%0,%1,%2,%3};\n"
        : "+f"(c[0]), "+f"(c[1]), "+f"(c[2]), "+f"(c[3])
        : "r"(a[0]), "r"(a[1]), "r"(a[2]), "r"(a[3]), "r"(b[0]), "r"(b[1]));
}
#endif

// smem (tcgen05): [0] tmem ptr, [8..24) mbar[2], [1024) A 32KB, [+32K) B0, B1
#define S_OFF_A   1024
#define S_OFF_B0  (S_OFF_A + 32768)
#define SMEM_TOT  (S_OFF_B0 + 2 * 32768)

__global__ void __launch_bounds__(256, 2) sim_kernel() {
    extern __shared__ __align__(1024) char smem[];
    const int tid  = threadIdx.x;
    const int ibase = blockIdx.x * BM;
    const int j0    = blockIdx.y * (NROWS / JSPLIT);

#if HAS_TC
    const uint32_t sb = smem_u32(smem);
    const int w    = tid >> 5, lane = tid & 31;
    const int sp   = w & 3, half = w >> 2;
    const int rg   = ibase + sp * 32 + lane;
    const float Cf = 14.4269504088896340737f;   // (1/T) * log2(e)

    if (w == 0)
        asm volatile("tcgen05.alloc.cta_group::1.sync.aligned.shared::cta.b32 [%0], 256;"
                     :: "r"(sb) : "memory");
    if (tid == 0) { MBAR_INIT(sb + 8); MBAR_INIT(sb + 16); }
    __syncthreads();
    uint32_t tmem;
    asm volatile("ld.shared.b32 %0, [%1];" : "=r"(tmem) : "r"(sb));

    for (int c = tid; c < 2048; c += 256) {
        int row = c >> 4, c16 = c & 15;
        uint4 v = *(const uint4*)(d_zb + (size_t)(ibase + row) * DD + c16 * 8);
        *(uint4*)(smem + S_OFF_A + tile_off(row, c16)) = v;
    }
    const uint64_t a_desc = make_desc(sb + S_OFF_A);

    float rowsum = 0.0f;

    for (int jt = 0; jt <= JT; ++jt) {
        const int p = jt & 1;
        if (jt < JT) {
            const int jb = j0 + jt * BN;
            char* bdst = smem + S_OFF_B0 + p * 32768;
            for (int c = tid; c < 2048; c += 256) {
                int row = c >> 4, c16 = c & 15;
                uint4 v = *(const uint4*)(d_zb + (size_t)(jb + row) * DD + c16 * 8);
                *(uint4*)(bdst + tile_off(row, c16)) = v;
            }
            FENCE_ASYNC();
            __syncthreads();
            if (tid == 0) {
                const uint64_t b_desc = make_desc(sb + S_OFF_B0 + p * 32768);
                const uint32_t dtm = tmem + p * 128;
                #pragma unroll
                for (int k = 0; k < 8; k++) {
                    uint32_t off = (k < 4) ? 2u * k : 1024u + 2u * (k - 4);
                    mma_f16_ss(dtm, a_desc + off, b_desc + off, k > 0);
                }
                TC_COMMIT(sb + 8 + p * 8);
            }
        }
        if (jt > 0) {
            const int q = (jt - 1) & 1;
            mbar_wait(sb + 8 + q * 8, ((jt - 1) >> 1) & 1);
            TC_FENCE_AFTER();
            const uint32_t taddr = tmem + q * 128 + ((uint32_t)sp << 21) + half * 64;
            uint32_t r0[32], r1[32];
            LDTM_X32(r0, taddr);
            LDTM_X32(r1, taddr + 32);
            TC_WAIT_LD();
            const int jb = j0 + (jt - 1) * BN;
            float s0 = 0.f, s1 = 0.f, s2 = 0.f, s3 = 0.f;
            if (jb != ibase) {
                #pragma unroll
                for (int j = 0; j < 32; j += 4) {
                    s0 += ex2f(__uint_as_float(r0[j + 0]) * Cf);
                    s1 += ex2f(__uint_as_float(r0[j + 1]) * Cf);
                    s2 += ex2f(__uint_as_float(r0[j + 2]) * Cf);
                    s3 += ex2f(__uint_as_float(r0[j + 3]) * Cf);
                }
                #pragma unroll
                for (int j = 0; j < 32; j += 4) {
                    s0 += ex2f(__uint_as_float(r1[j + 0]) * Cf);
                    s1 += ex2f(__uint_as_float(r1[j + 1]) * Cf);
                    s2 += ex2f(__uint_as_float(r1[j + 2]) * Cf);
                    s3 += ex2f(__uint_as_float(r1[j + 3]) * Cf);
                }
            } else {
                const int dcol = rg - jb - half * 64;
                #pragma unroll
                for (int j = 0; j < 32; j++) {
                    float e = ex2f(__uint_as_float(r0[j]) * Cf);
                    if (j != dcol) s0 += e;
                }
                #pragma unroll
                for (int j = 0; j < 32; j++) {
                    float e = ex2f(__uint_as_float(r1[j]) * Cf);
                    if (j + 32 != dcol) s1 += e;
                }
            }
            rowsum += (s0 + s1) + (s2 + s3);
            TC_FENCE_BEFORE();
        }
        __syncthreads();
    }

    atomicAdd(&d_S[rg], rowsum);

    __syncthreads();
    if (tid == 0) { MBAR_INVAL(sb + 8); MBAR_INVAL(sb + 16); }
    __syncthreads();
    if (w == 0) {
        asm volatile("tcgen05.relinquish_alloc_permit.cta_group::1.sync.aligned;");
        asm volatile("tcgen05.dealloc.cta_group::1.sync.aligned.b32 %0, 256;"
                     :: "r"(tmem));
    }
#else
    // ---------------- HMMA fallback (compiled for plain sm_103 pass) ----------------
    __nv_bfloat16* As = (__nv_bfloat16*)smem;
    __nv_bfloat16* Bs = As + BM * LDSTR;

    const int wid    = tid >> 5;
    const int lane   = tid & 31;
    const int g      = lane >> 2;
    const int q      = lane & 3;
    const int warp_m = wid & 3;
    const int warp_n = wid >> 2;

    for (int c = tid; c < BM * DD / 8; c += 256) {
        int row = c >> 4, c8 = c & 15;
        *(uint4*)(As + row * LDSTR + c8 * 8) =
            *(const uint4*)(d_zb + (size_t)(ibase + row) * DD + c8 * 8);
    }

    float rowsum[2][2] = {{0.f, 0.f}, {0.f, 0.f}};

    for (int jt = 0; jt < JT; ++jt) {
        const int jbase = j0 + jt * BN;
        __syncthreads();
        for (int c = tid; c < BN * DD / 8; c += 256) {
            int row = c >> 4, c8 = c & 15;
            *(uint4*)(Bs + row * LDSTR + c8 * 8) =
                *(const uint4*)(d_zb + (size_t)(jbase + row) * DD + c8 * 8);
        }
        __syncthreads();

        float acc[2][8][4];
        #pragma unroll
        for (int mf = 0; mf < 2; mf++)
            #pragma unroll
            for (int nf = 0; nf < 8; nf++)
                #pragma unroll
                for (int e = 0; e < 4; e++) acc[mf][nf][e] = 0.f;

        #pragma unroll
        for (int kk = 0; kk < 8; kk++) {
            const int kb = kk * 16;
            uint32_t a[2][4], b[8][2];
            #pragma unroll
            for (int mf = 0; mf < 2; mf++) {
                const __nv_bfloat16* p =
                    As + (warp_m * 32 + mf * 16 + g) * LDSTR + kb + 2 * q;
                a[mf][0] = *(const uint32_t*)p;
                a[mf][1] = *(const uint32_t*)(p + 8 * LDSTR);
                a[mf][2] = *(const uint32_t*)(p + 8);
                a[mf][3] = *(const uint32_t*)(p + 8 * LDSTR + 8);
            }
            #pragma unroll
            for (int nf = 0; nf < 8; nf++) {
                const __nv_bfloat16* p =
                    Bs + (warp_n * 64 + nf * 8 + g) * LDSTR + kb + 2 * q;
                b[nf][0] = *(const uint32_t*)p;
                b[nf][1] = *(const uint32_t*)(p + 8);
            }
            #pragma unroll
            for (int mf = 0; mf < 2; mf++)
                #pragma unroll
                for (int nf = 0; nf < 8; nf++)
                    mma16816(acc[mf][nf], a[mf], b[nf]);
        }

        #pragma unroll
        for (int mf = 0; mf < 2; mf++) {
            #pragma unroll
            for (int nf = 0; nf < 8; nf++) {
                #pragma unroll
                for (int e = 0; e < 4; e++) {
                    int rgl = ibase + warp_m * 32 + mf * 16 + g + ((e >> 1) << 3);
                    int cg  = jbase + warp_n * 64 + nf * 8 + q * 2 + (e & 1);
                    float ev = (rgl == cg) ? 0.f : __expf(acc[mf][nf][e] * 10.0f);
                    rowsum[mf][e >> 1] += ev;
                }
            }
        }
    }

    #pragma unroll
    for (int mf = 0; mf < 2; mf++) {
        #pragma unroll
        for (int h = 0; h < 2; h++) {
            float s = rowsum[mf][h];
            s += __shfl_xor_sync(0xffffffffu, s, 1);
            s += __shfl_xor_sync(0xffffffffu, s, 2);
            if (q == 0)
                atomicAdd(&d_S[ibase + warp_m * 32 + mf * 16 + g + h * 8], s);
        }
    }
#endif
}

// ------------------------------------------------------------------ final reduce
__global__ void final_kernel(float* out) {
    __shared__ double red[1024];
    int tid = threadIdx.x;
    double s = 0.0;
    for (int r = tid; r < NROWS; r += 1024) s += (double)logf(d_S[r]);
    for (int i = tid; i < NB;    i += 1024) s -= 20.0 * (double)d_pos[i];
    red[tid] = s;
    __syncthreads();
    #pragma unroll
    for (int st = 512; st; st >>= 1) {
        if (tid < st) red[tid] += red[tid + st];
        __syncthreads();
    }
    if (tid == 0) out[0] = (float)(red[0] / (double)NROWS);
}

// ------------------------------------------------------------------ launch
extern "C" void kernel_launch(void* const* d_in, const int* in_sizes, int n_in,
                              void* d_out, int out_size) {
    const float* xi = (const float*)d_in[0];
    const float* xj = (const float*)d_in[1];
    float* out = (float*)d_out;

    cudaFuncSetAttribute(sim_kernel,
                         cudaFuncAttributeMaxDynamicSharedMemorySize, SMEM_TOT);

    normalize_kernel<<<NROWS / 8, 256>>>(xi, xj);
    pos_kernel<<<NB / 8, 256>>>();
    dim3 grid(NROWS / BM, JSPLIT);
    sim_kernel<<<grid, 256, SMEM_TOT>>>();
    final_kernel<<<1, 1024>>>(out);
}

// round 5
// speedup vs baseline: 1.6420x; 1.1474x over previous
#include <cuda_runtime.h>
#include <cuda_bf16.h>
#include <cuda_fp16.h>
#include <stdint.h>

#define NB     4096
#define NROWS  8192
#define DD     128
#define BM     128
#define BN     128
#define JSPLIT 4
#define JT     (NROWS / JSPLIT / BN)   // 16
#define LDSTR  136                      // fallback smem stride

// tcgen05 only exists in the arch-specific (sm_103a/sm_100a) compilation pass.
#if !defined(__CUDA_ARCH__) || defined(__CUDA_ARCH_FEAT_SM103_ALL) || \
    defined(__CUDA_ARCH_FEAT_SM100_ALL) || defined(__CUDA_ARCH_SPECIFIC__) || \
    defined(__CUDA_ARCH_FAMILY_SPECIFIC__)
#define HAS_TC 1
#else
#define HAS_TC 0
#endif

__device__ __align__(16) __nv_bfloat16  d_zb[NROWS * DD];
__device__ float  d_S  [NROWS];
__device__ float  d_pos[NB];
__device__ double d_part[32];

// ------------------------------------------------------------------ utils
__device__ __forceinline__ uint32_t smem_u32(const void* p) {
    uint32_t a;
    asm("{ .reg .u64 t; cvta.to.shared.u64 t, %1; cvt.u32.u64 %0, t; }"
        : "=r"(a) : "l"(p));
    return a;
}
__device__ __forceinline__ float ex2f(float x) {
    float y; asm("ex2.approx.ftz.f32 %0, %1;" : "=f"(y) : "f"(x)); return y;
}

// ------------------------------------------------------------------ normalize (+zero S)
__global__ void normalize_kernel(const float* __restrict__ xi,
                                 const float* __restrict__ xj) {
    int t = blockIdx.x * blockDim.x + threadIdx.x;
    if (t < NROWS) d_S[t] = 0.0f;
    int warp = t >> 5;
    int lane = threadIdx.x & 31;
    if (warp >= NROWS) return;
    const float* src = (warp < NB) ? (xi + (size_t)warp * DD)
                                   : (xj + (size_t)(warp - NB) * DD);
    float4 v = ((const float4*)src)[lane];
    float s = v.x*v.x + v.y*v.y + v.z*v.z + v.w*v.w;
    #pragma unroll
    for (int o = 16; o; o >>= 1) s += __shfl_xor_sync(0xffffffffu, s, o);
    float inv = 1.0f / fmaxf(sqrtf(s), 1e-12f);
    __nv_bfloat162* zb = (__nv_bfloat162*)(d_zb + (size_t)warp * DD);
    zb[lane*2 + 0] = __floats2bfloat162_rn(v.x*inv, v.y*inv);
    zb[lane*2 + 1] = __floats2bfloat162_rn(v.z*inv, v.w*inv);
}

// ------------------------------------------------------------------ positives (fp32 from bf16 z)
__global__ void pos_kernel() {
    int warp = (blockIdx.x * blockDim.x + threadIdx.x) >> 5;
    int lane = threadIdx.x & 31;
    if (warp >= NB) return;
    const uint2* pa = (const uint2*)(d_zb + (size_t)warp        * DD);
    const uint2* pb = (const uint2*)(d_zb + (size_t)(warp + NB) * DD);
    uint2 ua = pa[lane], ub = pb[lane];
    float2 a0 = __bfloat1622float2(*(__nv_bfloat162*)&ua.x);
    float2 a1 = __bfloat1622float2(*(__nv_bfloat162*)&ua.y);
    float2 b0 = __bfloat1622float2(*(__nv_bfloat162*)&ub.x);
    float2 b1 = __bfloat1622float2(*(__nv_bfloat162*)&ub.y);
    float s = a0.x*b0.x + a0.y*b0.y + a1.x*b1.x + a1.y*b1.y;
    #pragma unroll
    for (int o = 16; o; o >>= 1) s += __shfl_xor_sync(0xffffffffu, s, o);
    if (lane == 0) d_pos[warp] = s;
}

// ================================================================== tcgen05 path
#if HAS_TC
#define DESC_BASE ((2ull << 61) | (1ull << 46) | (64ull << 32) | (1ull << 16))
__device__ __forceinline__ uint64_t make_desc(uint32_t addr) {
    return DESC_BASE | ((uint64_t)(addr >> 4) & 0x3FFF);
}
// idesc kind::f16: dtype=F32, a=BF16, b=BF16 (K-major), N=128, M=128 (proven)
#define MMA_IDESC 0x8200490u

__device__ __forceinline__ void mma_f16_ss(uint32_t d, uint64_t a, uint64_t b,
                                           uint32_t en) {
    asm volatile(
        "{\n\t.reg .pred p;\n\t"
        "setp.ne.u32 p, %4, 0;\n\t"
        "tcgen05.mma.cta_group::1.kind::f16 [%0], %1, %2, %3, {%5,%5,%5,%5}, p;\n\t}"
        :: "r"(d), "l"(a), "l"(b), "r"(MMA_IDESC), "r"(en), "r"(0u) : "memory");
}

#define MBAR_INIT(a)   asm volatile("mbarrier.init.shared.b64 [%0], 1;" :: "r"(a) : "memory")
#define MBAR_INVAL(a)  asm volatile("mbarrier.inval.shared.b64 [%0];"   :: "r"(a) : "memory")
#define TC_COMMIT(a)   asm volatile("tcgen05.commit.cta_group::1.mbarrier::arrive::one.shared::cluster.b64 [%0];" :: "r"(a) : "memory")
#define TC_FENCE_AFTER()  asm volatile("tcgen05.fence::after_thread_sync;"  ::: "memory")
#define TC_FENCE_BEFORE() asm volatile("tcgen05.fence::before_thread_sync;" ::: "memory")
#define TC_WAIT_LD()      asm volatile("tcgen05.wait::ld.sync.aligned;"     ::: "memory")
#define FENCE_ASYNC()     asm volatile("fence.proxy.async.shared::cta;"     ::: "memory")

__device__ __forceinline__ void mbar_wait(uint32_t mbar, uint32_t parity) {
    uint32_t done;
    asm volatile(
        "{\n\t.reg .pred p;\n\t"
        "mbarrier.try_wait.parity.acquire.cta.shared::cta.b64 p, [%1], %2;\n\t"
        "selp.b32 %0, 1, 0, p;\n\t}"
        : "=r"(done) : "r"(mbar), "r"(parity) : "memory");
    if (!done) {
        asm volatile(
            "{\n\t.reg .pred P1;\n\t"
            "WL_%=:\n\t"
            "mbarrier.try_wait.parity.acquire.cta.shared::cta.b64 P1, [%0], %1, 0x989680;\n\t"
            "@P1 bra.uni WD_%=;\n\t"
            "bra.uni WL_%=;\n\t"
            "WD_%=:\n\t}"
            :: "r"(mbar), "r"(parity) : "memory");
    }
}

#define LDTM_X32(r, a) \
    asm volatile("tcgen05.ld.sync.aligned.32x32b.x32.b32 " \
        "{%0,%1,%2,%3,%4,%5,%6,%7,%8,%9,%10,%11,%12,%13,%14,%15," \
        "%16,%17,%18,%19,%20,%21,%22,%23,%24,%25,%26,%27,%28,%29,%30,%31}, [%32];" \
        : "=r"((r)[0]),"=r"((r)[1]),"=r"((r)[2]),"=r"((r)[3]), \
          "=r"((r)[4]),"=r"((r)[5]),"=r"((r)[6]),"=r"((r)[7]), \
          "=r"((r)[8]),"=r"((r)[9]),"=r"((r)[10]),"=r"((r)[11]), \
          "=r"((r)[12]),"=r"((r)[13]),"=r"((r)[14]),"=r"((r)[15]), \
          "=r"((r)[16]),"=r"((r)[17]),"=r"((r)[18]),"=r"((r)[19]), \
          "=r"((r)[20]),"=r"((r)[21]),"=r"((r)[22]),"=r"((r)[23]), \
          "=r"((r)[24]),"=r"((r)[25]),"=r"((r)[26]),"=r"((r)[27]), \
          "=r"((r)[28]),"=r"((r)[29]),"=r"((r)[30]),"=r"((r)[31]) \
        : "r"(a))
#endif  // HAS_TC

// blocked-atom SW128 byte offset for (row, 16B-chunk) of a 128x128 bf16 tile
__device__ __forceinline__ uint32_t tile_off(int row, int c16) {
    uint32_t byte = (uint32_t)(((row >> 3) + ((c16 >> 3) << 4)) * 1024
                               + (row & 7) * 128 + (c16 & 7) * 16);
    return byte ^ ((byte >> 3) & 0x70);
}

#if !HAS_TC
__device__ __forceinline__ void mma16816(float c[4], const uint32_t a[4],
                                         const uint32_t b[2]) {
    asm volatile(
        "mma.sync.aligned.m16n8k16.row.col.f32.bf16.bf16.f32 "
        "{%0,%1,%2,%3}, {%4,%5,%6,%7}, {%8,%9}, {%0,%1,%2,%3};\n"
        : "+f"(c[0]), "+f"(c[1]), "+f"(c[2]), "+f"(c[3])
        : "r"(a[0]), "r"(a[1]), "r"(a[2]), "r"(a[3]), "r"(b[0]), "r"(b[1]));
}
#endif

// smem: [0] tmem ptr, [8..24) mbar[2], [1024) A 32KB, [+32K) B0, B1
#define S_OFF_A   1024
#define S_OFF_B0  (S_OFF_A + 32768)
#define SMEM_TOT  (S_OFF_B0 + 2 * 32768)

__global__ void __launch_bounds__(256, 2) sim_kernel() {
    extern __shared__ __align__(1024) char smem[];
    const int tid   = threadIdx.x;
    const int ibase = blockIdx.x * BM;
    const int j0    = blockIdx.y * (NROWS / JSPLIT);

#if HAS_TC
    const uint32_t sb = smem_u32(smem);
    const int w    = tid >> 5, lane = tid & 31;
    const int sp   = w & 3, half = w >> 2;
    const int rg   = ibase + sp * 32 + lane;
    const float Cf = 14.4269504088896340737f;   // (1/T) * log2(e)
    uint32_t cf2;
    { __half2 h2 = __float2half2_rn(Cf); cf2 = *(uint32_t*)&h2; }

    if (w == 0)
        asm volatile("tcgen05.alloc.cta_group::1.sync.aligned.shared::cta.b32 [%0], 256;"
                     :: "r"(sb) : "memory");
    if (tid == 0) { MBAR_INIT(sb + 8); MBAR_INIT(sb + 16); }
    __syncthreads();
    uint32_t tmem;
    asm volatile("ld.shared.b32 %0, [%1];" : "=r"(tmem) : "r"(sb));

    for (int c = tid; c < 2048; c += 256) {
        int row = c >> 4, c16 = c & 15;
        uint4 v = *(const uint4*)(d_zb + (size_t)(ibase + row) * DD + c16 * 8);
        *(uint4*)(smem + S_OFF_A + tile_off(row, c16)) = v;
    }
    const uint64_t a_desc = make_desc(sb + S_OFF_A);

    float rowsum = 0.0f;

    for (int jt = 0; jt <= JT; ++jt) {
        const int p = jt & 1;
        if (jt < JT) {
            const int jb = j0 + jt * BN;
            char* bdst = smem + S_OFF_B0 + p * 32768;
            for (int c = tid; c < 2048; c += 256) {
                int row = c >> 4, c16 = c & 15;
                uint4 v = *(const uint4*)(d_zb + (size_t)(jb + row) * DD + c16 * 8);
                *(uint4*)(bdst + tile_off(row, c16)) = v;
            }
            FENCE_ASYNC();
            __syncthreads();
            if (tid == 0) {
                const uint64_t b_desc = make_desc(sb + S_OFF_B0 + p * 32768);
                const uint32_t dtm = tmem + p * 128;
                #pragma unroll
                for (int k = 0; k < 8; k++) {
                    uint32_t off = (k < 4) ? 2u * k : 1024u + 2u * (k - 4);
                    mma_f16_ss(dtm, a_desc + off, b_desc + off, k > 0);
                }
                TC_COMMIT(sb + 8 + p * 8);
            }
        }
        if (jt > 0) {
            const int q = (jt - 1) & 1;
            mbar_wait(sb + 8 + q * 8, ((jt - 1) >> 1) & 1);
            TC_FENCE_AFTER();
            const uint32_t taddr = tmem + q * 128 + ((uint32_t)sp << 21) + half * 64;
            uint32_t r0[32], r1[32];
            LDTM_X32(r0, taddr);
            LDTM_X32(r1, taddr + 32);
            TC_WAIT_LD();
            const int jb1 = j0 + (jt - 1) * BN;
            if (jb1 != ibase) {
                // f16x2 exp: one MUFU per 2 elements, f16x2 chunk accumulators
                uint32_t acc[4];
                { __half2 z2 = __float2half2_rn(0.f);
                  acc[0] = acc[1] = acc[2] = acc[3] = *(uint32_t*)&z2; }
                #pragma unroll
                for (int j = 0; j < 32; j += 2) {
                    uint32_t h, e;
                    asm("cvt.rn.f16x2.f32 %0, %1, %2;" : "=r"(h)
                        : "f"(__uint_as_float(r0[j + 1])), "f"(__uint_as_float(r0[j])));
                    asm("mul.f16x2 %0, %1, %2;" : "=r"(h) : "r"(h), "r"(cf2));
                    asm("ex2.approx.f16x2 %0, %1;" : "=r"(e) : "r"(h));
                    asm("add.f16x2 %0, %1, %2;" : "=r"(acc[(j >> 1) & 3])
                        : "r"(acc[(j >> 1) & 3]), "r"(e));
                }
                #pragma unroll
                for (int j = 0; j < 32; j += 2) {
                    uint32_t h, e;
                    asm("cvt.rn.f16x2.f32 %0, %1, %2;" : "=r"(h)
                        : "f"(__uint_as_float(r1[j + 1])), "f"(__uint_as_float(r1[j])));
                    asm("mul.f16x2 %0, %1, %2;" : "=r"(h) : "r"(h), "r"(cf2));
                    asm("ex2.approx.f16x2 %0, %1;" : "=r"(e) : "r"(h));
                    asm("add.f16x2 %0, %1, %2;" : "=r"(acc[(j >> 1) & 3])
                        : "r"(acc[(j >> 1) & 3]), "r"(e));
                }
                #pragma unroll
                for (int u = 0; u < 4; u++) {
                    float2 f = __half22float2(*(__half2*)&acc[u]);
                    rowsum += f.x + f.y;
                }
            } else {
                // diagonal tile: exact f32 path with masking
                const int dcol = rg - jb1 - half * 64;
                float s0 = 0.f, s1 = 0.f;
                #pragma unroll
                for (int j = 0; j < 32; j++) {
                    float e = ex2f(__uint_as_float(r0[j]) * Cf);
                    if (j != dcol) s0 += e;
                }
                #pragma unroll
                for (int j = 0; j < 32; j++) {
                    float e = ex2f(__uint_as_float(r1[j]) * Cf);
                    if (j + 32 != dcol) s1 += e;
                }
                rowsum += s0 + s1;
            }
            TC_FENCE_BEFORE();
        }
        __syncthreads();
    }

    atomicAdd(&d_S[rg], rowsum);

    __syncthreads();
    if (tid == 0) { MBAR_INVAL(sb + 8); MBAR_INVAL(sb + 16); }
    __syncthreads();
    if (w == 0) {
        asm volatile("tcgen05.relinquish_alloc_permit.cta_group::1.sync.aligned;");
        asm volatile("tcgen05.dealloc.cta_group::1.sync.aligned.b32 %0, 256;"
                     :: "r"(tmem));
    }
#else
    // ---------------- HMMA fallback (plain sm_103 pass; never runs on GB300) ------
    __nv_bfloat16* As = (__nv_bfloat16*)smem;
    __nv_bfloat16* Bs = As + BM * LDSTR;

    const int wid    = tid >> 5;
    const int lane   = tid & 31;
    const int g      = lane >> 2;
    const int q      = lane & 3;
    const int warp_m = wid & 3;
    const int warp_n = wid >> 2;

    for (int c = tid; c < BM * DD / 8; c += 256) {
        int row = c >> 4, c8 = c & 15;
        *(uint4*)(As + row * LDSTR + c8 * 8) =
            *(const uint4*)(d_zb + (size_t)(ibase + row) * DD + c8 * 8);
    }

    float rowsum[2][2] = {{0.f, 0.f}, {0.f, 0.f}};

    for (int jt = 0; jt < JT; ++jt) {
        const int jbase = j0 + jt * BN;
        __syncthreads();
        for (int c = tid; c < BN * DD / 8; c += 256) {
            int row = c >> 4, c8 = c & 15;
            *(uint4*)(Bs + row * LDSTR + c8 * 8) =
                *(const uint4*)(d_zb + (size_t)(jbase + row) * DD + c8 * 8);
        }
        __syncthreads();

        float acc[2][8][4];
        #pragma unroll
        for (int mf = 0; mf < 2; mf++)
            #pragma unroll
            for (int nf = 0; nf < 8; nf++)
                #pragma unroll
                for (int e = 0; e < 4; e++) acc[mf][nf][e] = 0.f;

        #pragma unroll
        for (int kk = 0; kk < 8; kk++) {
            const int kb = kk * 16;
            uint32_t a[2][4], b[8][2];
            #pragma unroll
            for (int mf = 0; mf < 2; mf++) {
                const __nv_bfloat16* pp =
                    As + (warp_m * 32 + mf * 16 + g) * LDSTR + kb + 2 * q;
                a[mf][0] = *(const uint32_t*)pp;
                a[mf][1] = *(const uint32_t*)(pp + 8 * LDSTR);
                a[mf][2] = *(const uint32_t*)(pp + 8);
                a[mf][3] = *(const uint32_t*)(pp + 8 * LDSTR + 8);
            }
            #pragma unroll
            for (int nf = 0; nf < 8; nf++) {
                const __nv_bfloat16* pp =
                    Bs + (warp_n * 64 + nf * 8 + g) * LDSTR + kb + 2 * q;
                b[nf][0] = *(const uint32_t*)pp;
                b[nf][1] = *(const uint32_t*)(pp + 8);
            }
            #pragma unroll
            for (int mf = 0; mf < 2; mf++)
                #pragma unroll
                for (int nf = 0; nf < 8; nf++)
                    mma16816(acc[mf][nf], a[mf], b[nf]);
        }

        #pragma unroll
        for (int mf = 0; mf < 2; mf++)
            #pragma unroll
            for (int nf = 0; nf < 8; nf++)
                #pragma unroll
                for (int e = 0; e < 4; e++) {
                    int rgl = ibase + warp_m * 32 + mf * 16 + g + ((e >> 1) << 3);
                    int cg  = jbase + warp_n * 64 + nf * 8 + q * 2 + (e & 1);
                    float ev = (rgl == cg) ? 0.f : __expf(acc[mf][nf][e] * 10.0f);
                    rowsum[mf][e >> 1] += ev;
                }
    }

    #pragma unroll
    for (int mf = 0; mf < 2; mf++)
        #pragma unroll
        for (int h = 0; h < 2; h++) {
            float s = rowsum[mf][h];
            s += __shfl_xor_sync(0xffffffffu, s, 1);
            s += __shfl_xor_sync(0xffffffffu, s, 2);
            if (q == 0)
                atomicAdd(&d_S[ibase + warp_m * 32 + mf * 16 + g + h * 8], s);
        }
#endif
}

// ------------------------------------------------------------------ two-stage final reduce
__global__ void reduceA_kernel() {
    __shared__ double red[256];
    const int b = blockIdx.x, tid = threadIdx.x;
    double s = (double)__logf(d_S[b * 256 + tid]);
    if (tid < 128) s -= 20.0 * (double)d_pos[b * 128 + tid];
    red[tid] = s;
    __syncthreads();
    #pragma unroll
    for (int st = 128; st; st >>= 1) {
        if (tid < st) red[tid] += red[tid + st];
        __syncthreads();
    }
    if (tid == 0) d_part[b] = red[0];
}

__global__ void reduceB_kernel(float* out) {
    double s = d_part[threadIdx.x];
    #pragma unroll
    for (int o = 16; o; o >>= 1) s += __shfl_xor_sync(0xffffffffu, s, o);
    if (threadIdx.x == 0) out[0] = (float)(s / (double)NROWS);
}

// ------------------------------------------------------------------ launch
extern "C" void kernel_launch(void* const* d_in, const int* in_sizes, int n_in,
                              void* d_out, int out_size) {
    const float* xi = (const float*)d_in[0];
    const float* xj = (const float*)d_in[1];
    float* out = (float*)d_out;

    cudaFuncSetAttribute(sim_kernel,
                         cudaFuncAttributeMaxDynamicSharedMemorySize, SMEM_TOT);

    normalize_kernel<<<NROWS / 8, 256>>>(xi, xj);
    pos_kernel<<<NB / 8, 256>>>();
    dim3 grid(NROWS / BM, JSPLIT);
    sim_kernel<<<grid, 256, SMEM_TOT>>>();
    reduceA_kernel<<<32, 256>>>();
    reduceB_kernel<<<1, 32>>>(out);
}